// round 1
// baseline (speedup 1.0000x reference)
#include <cuda_runtime.h>

#define BATCH  16
#define SEQ    1024
#define HDIM   768
#define NHEADS 12
#define HD     64
#define MTOK   (BATCH*SEQ)      /* 16384 */
#define QKVN   (3*HDIM)         /* 2304  */

// Scratch (allocation-free rule: __device__ globals). 4 x 48MB = 192MB.
__device__ float g_Q[BATCH*NHEADS*SEQ*HD];
__device__ float g_K[BATCH*NHEADS*SEQ*HD];
__device__ float g_V[BATCH*NHEADS*SEQ*HD];
__device__ float g_AttO[MTOK*HDIM];

// ---------------------------------------------------------------------------
// SGEMM: C[M, Ncols] = A[M,768] @ W[768,Ncols] + bias
// MODE 0: A = x, scatter into g_Q/g_K/g_V (head-major [B,NH,N,64])
// MODE 1: A = g_AttO, write dense to out[M,768]
// 128x128 block tile, Kt=8, 256 threads, 8x8 per-thread micro-tile.
// ---------------------------------------------------------------------------
template<int MODE>
__global__ __launch_bounds__(256)
void sgemm_kernel(const float* __restrict__ A, const float* __restrict__ W,
                  const float* __restrict__ bias, float* __restrict__ out,
                  int Ncols)
{
    __shared__ float As[8][132];   // transposed A tile [k][m], padded vs conflicts
    __shared__ float Bs[8][128];   // natural B tile [k][n]

    const int tid = threadIdx.x;
    const int m0  = blockIdx.y * 128;
    const int c0  = blockIdx.x * 128;
    const int ty  = tid >> 4;       // 0..15 -> rows ty*8..
    const int tx  = tid & 15;       // 0..15 -> cols tx*8..

    const float* Ap = (MODE == 0) ? A : g_AttO;

    // global-load assignments (each thread: 4 floats of A, 4 floats of B)
    const int ar = tid >> 1;         // 0..127
    const int ac = (tid & 1) * 4;    // 0 or 4
    const int br = tid >> 5;         // 0..7
    const int bc = (tid & 31) * 4;   // 0..124

    float acc[8][8];
#pragma unroll
    for (int i = 0; i < 8; i++)
#pragma unroll
        for (int j = 0; j < 8; j++) acc[i][j] = 0.f;

    for (int kb = 0; kb < HDIM; kb += 8) {
        float4 av = *reinterpret_cast<const float4*>(Ap + (size_t)(m0 + ar) * HDIM + kb + ac);
        float4 bv = *reinterpret_cast<const float4*>(W  + (size_t)(kb + br) * Ncols + c0 + bc);
        As[ac + 0][ar] = av.x; As[ac + 1][ar] = av.y;
        As[ac + 2][ar] = av.z; As[ac + 3][ar] = av.w;
        *reinterpret_cast<float4*>(&Bs[br][bc]) = bv;
        __syncthreads();

#pragma unroll
        for (int k = 0; k < 8; k++) {
            float a[8], b[8];
            *(float4*)&a[0] = *(const float4*)&As[k][ty * 8];
            *(float4*)&a[4] = *(const float4*)&As[k][ty * 8 + 4];
            *(float4*)&b[0] = *(const float4*)&Bs[k][tx * 8];
            *(float4*)&b[4] = *(const float4*)&Bs[k][tx * 8 + 4];
#pragma unroll
            for (int i = 0; i < 8; i++)
#pragma unroll
                for (int j = 0; j < 8; j++) acc[i][j] = fmaf(a[i], b[j], acc[i][j]);
        }
        __syncthreads();
    }

    if (MODE == 0) {
        // 8 consecutive output cols always stay inside one 64-wide head slice
        const int cbase = c0 + tx * 8;
        const int part  = cbase / HDIM;                 // 0=Q 1=K 2=V
        const int cc    = cbase - part * HDIM;
        const int h     = cc >> 6;
        const int dbase = cc & 63;
        float* dst = (part == 0) ? g_Q : (part == 1 ? g_K : g_V);
#pragma unroll
        for (int i = 0; i < 8; i++) {
            int m = m0 + ty * 8 + i;
            int bi = m >> 10, n = m & (SEQ - 1);
            float* p = dst + ((size_t)(bi * NHEADS + h) * SEQ + n) * HD + dbase;
#pragma unroll
            for (int j = 0; j < 8; j++) p[j] = acc[i][j] + bias[cbase + j];
        }
    } else {
#pragma unroll
        for (int i = 0; i < 8; i++) {
            int m = m0 + ty * 8 + i;
            float* p = out + (size_t)m * HDIM + c0 + tx * 8;
#pragma unroll
            for (int j = 0; j < 8; j++) p[j] = acc[i][j] + bias[c0 + tx * 8 + j];
        }
    }
}

// ---------------------------------------------------------------------------
// Flash attention (fp32). One block = one (b, h, 64-row q tile).
// 64 threads; each thread owns an 8x8 micro-tile (rows ty*8.., cols tx*8..).
// smem: Qs [d][row] (pre-scaled), Ks [d][col] (reused as P^T [k][row]),
//       Vs [k][d].  3 * 64*64 * 4B = 49152B static (exactly 48KB).
// ---------------------------------------------------------------------------
__global__ __launch_bounds__(64)
void attn_kernel()
{
    __shared__ float Qs[64][64];
    __shared__ float Ks[64][64];
    __shared__ float Vs[64][64];

    const int tid = threadIdx.x;
    const int tx  = tid & 7;     // col group
    const int ty  = tid >> 3;    // row group
    const int b   = blockIdx.z, h = blockIdx.y;
    const int q0  = blockIdx.x * 64;

    const float* Qg = g_Q + (size_t)((b * NHEADS + h) * SEQ + q0) * HD;
    const float* Kg = g_K + (size_t)((b * NHEADS + h) * SEQ) * HD;
    const float* Vg = g_V + (size_t)((b * NHEADS + h) * SEQ) * HD;

    // Load Q transposed + pre-scaled by 1/sqrt(64)
    for (int f = tid; f < 1024; f += 64) {            // f = float4 index
        int r = f >> 4, c4 = (f & 15) << 2;
        float4 v = *reinterpret_cast<const float4*>(Qg + r * HD + c4);
        Qs[c4 + 0][r] = v.x * 0.125f; Qs[c4 + 1][r] = v.y * 0.125f;
        Qs[c4 + 2][r] = v.z * 0.125f; Qs[c4 + 3][r] = v.w * 0.125f;
    }

    float o[8][8], mrow[8], lrow[8];
#pragma unroll
    for (int i = 0; i < 8; i++) {
        mrow[i] = -1e30f; lrow[i] = 0.f;
#pragma unroll
        for (int j = 0; j < 8; j++) o[i][j] = 0.f;
    }

    for (int kt = 0; kt < SEQ / 64; kt++) {
        __syncthreads();   // previous iteration done with Ks(P)/Vs
        const float* Kt = Kg + (size_t)kt * 64 * HD;
        const float* Vt = Vg + (size_t)kt * 64 * HD;
        for (int f = tid; f < 1024; f += 64) {
            int r = f >> 4, c4 = (f & 15) << 2;
            float4 kv = *reinterpret_cast<const float4*>(Kt + r * HD + c4);
            Ks[c4 + 0][r] = kv.x; Ks[c4 + 1][r] = kv.y;
            Ks[c4 + 2][r] = kv.z; Ks[c4 + 3][r] = kv.w;
            float4 vv = *reinterpret_cast<const float4*>(Vt + r * HD + c4);
            *reinterpret_cast<float4*>(&Vs[r][c4]) = vv;
        }
        __syncthreads();

        // S = (Q * scale) @ K^T  (64x64 tile)
        float s[8][8];
#pragma unroll
        for (int i = 0; i < 8; i++)
#pragma unroll
            for (int j = 0; j < 8; j++) s[i][j] = 0.f;
        for (int d = 0; d < 64; d++) {
            float qa[8], kb[8];
            *(float4*)&qa[0] = *(const float4*)&Qs[d][ty * 8];
            *(float4*)&qa[4] = *(const float4*)&Qs[d][ty * 8 + 4];
            *(float4*)&kb[0] = *(const float4*)&Ks[d][tx * 8];
            *(float4*)&kb[4] = *(const float4*)&Ks[d][tx * 8 + 4];
#pragma unroll
            for (int i = 0; i < 8; i++)
#pragma unroll
                for (int j = 0; j < 8; j++) s[i][j] = fmaf(qa[i], kb[j], s[i][j]);
        }

        // Online softmax (row stats shared across the 8 lanes of a row group)
#pragma unroll
        for (int i = 0; i < 8; i++) {
            float mx = s[i][0];
#pragma unroll
            for (int j = 1; j < 8; j++) mx = fmaxf(mx, s[i][j]);
            mx = fmaxf(mx, __shfl_xor_sync(0xffffffffu, mx, 1));
            mx = fmaxf(mx, __shfl_xor_sync(0xffffffffu, mx, 2));
            mx = fmaxf(mx, __shfl_xor_sync(0xffffffffu, mx, 4));
            float mnew = fmaxf(mrow[i], mx);
            float corr = __expf(mrow[i] - mnew);
            float rs = 0.f;
#pragma unroll
            for (int j = 0; j < 8; j++) {
                float p = __expf(s[i][j] - mnew);
                s[i][j] = p; rs += p;
            }
            rs += __shfl_xor_sync(0xffffffffu, rs, 1);
            rs += __shfl_xor_sync(0xffffffffu, rs, 2);
            rs += __shfl_xor_sync(0xffffffffu, rs, 4);
            lrow[i] = lrow[i] * corr + rs;
            mrow[i] = mnew;
#pragma unroll
            for (int j = 0; j < 8; j++) o[i][j] *= corr;
        }

        __syncthreads();   // everyone done reading Ks as K
        // Store P^T into Ks buffer: Ks[k][row]
#pragma unroll
        for (int i = 0; i < 8; i++)
#pragma unroll
            for (int j = 0; j < 8; j++) Ks[tx * 8 + j][ty * 8 + i] = s[i][j];
        __syncthreads();

        // O += P @ V
        for (int k = 0; k < 64; k++) {
            float pa[8], vb[8];
            *(float4*)&pa[0] = *(const float4*)&Ks[k][ty * 8];
            *(float4*)&pa[4] = *(const float4*)&Ks[k][ty * 8 + 4];
            *(float4*)&vb[0] = *(const float4*)&Vs[k][tx * 8];
            *(float4*)&vb[4] = *(const float4*)&Vs[k][tx * 8 + 4];
#pragma unroll
            for (int i = 0; i < 8; i++)
#pragma unroll
                for (int j = 0; j < 8; j++) o[i][j] = fmaf(pa[i], vb[j], o[i][j]);
        }
    }

    // Normalize + write to [B, N, H] layout (heads concatenated)
#pragma unroll
    for (int i = 0; i < 8; i++) {
        float inv = 1.f / lrow[i];
        int n = q0 + ty * 8 + i;
        float* p = g_AttO + (size_t)(b * SEQ + n) * HDIM + h * HD + tx * 8;
#pragma unroll
        for (int j = 0; j < 8; j++) p[j] = o[i][j] * inv;
    }
}

// ---------------------------------------------------------------------------
extern "C" void kernel_launch(void* const* d_in, const int* in_sizes, int n_in,
                              void* d_out, int out_size)
{
    const float* x     = (const float*)d_in[0];
    const float* w_qkv = (const float*)d_in[1];
    const float* b_qkv = (const float*)d_in[2];
    const float* w_out = (const float*)d_in[3];
    const float* b_out = (const float*)d_in[4];
    float* out = (float*)d_out;
    (void)in_sizes; (void)n_in; (void)out_size;

    dim3 g1(QKVN / 128, MTOK / 128);                 // 18 x 128 blocks
    sgemm_kernel<0><<<g1, 256>>>(x, w_qkv, b_qkv, nullptr, QKVN);

    dim3 g2(SEQ / 64, NHEADS, BATCH);                // 16 x 12 x 16 blocks
    attn_kernel<<<g2, 64>>>();

    dim3 g3(HDIM / 128, MTOK / 128);                 // 6 x 128 blocks
    sgemm_kernel<1><<<g3, 256>>>(nullptr, w_out, b_out, out, HDIM);
}

// round 9
// speedup vs baseline: 1.0029x; 1.0029x over previous
#include <cuda_runtime.h>

#define BATCH  16
#define SEQ    1024
#define HDIM   768
#define NHEADS 12
#define HD     64
#define MTOK   (BATCH*SEQ)      /* 16384 */
#define QKVN   (3*HDIM)         /* 2304  */

// ------------------------- device scratch (no alloc rule) -------------------
__device__ __align__(256) float g_Q[BATCH*NHEADS*SEQ*HD];
__device__ __align__(256) float g_K[BATCH*NHEADS*SEQ*HD];
__device__ __align__(256) float g_V[BATCH*NHEADS*SEQ*HD];
__device__ __align__(256) float g_AttO[MTOK*HDIM];

// Fast exp2 on (-inf, 0]: degree-6 Taylor of 2^f on [0,1) + exponent bits.
// rel err ~2e-5. All fma/alu pipe, no MUFU.
__device__ __forceinline__ float exp2f_fast(float x) {
    x = fmaxf(x, -125.0f);
    float t = floorf(x);
    float f = x - t;
    float p = 1.5403530e-4f;
    p = fmaf(p, f, 1.3333558e-3f);
    p = fmaf(p, f, 9.6181291e-3f);
    p = fmaf(p, f, 5.5504109e-2f);
    p = fmaf(p, f, 2.4022651e-1f);
    p = fmaf(p, f, 6.9314718e-1f);
    p = fmaf(p, f, 1.0f);
    int e = (int)t;
    return p * __int_as_float((e + 127) << 23);
}

// ---------------------------------------------------------------------------
// SGEMM: C[M, Ncols] = A[M,768] @ W[768,Ncols] + bias
// 128x128 tile, 256 thr, 8x8 microtile. KB=16, double-buffered smem with
// register prefetch: one __syncthreads per 16 k-steps.
// MODE 0: A = x, scatter into g_Q/g_K/g_V head-major. MODE 1: dense out.
// ---------------------------------------------------------------------------
#define KB     16
#define NCHUNK (HDIM / KB)      /* 48 */

template<int MODE>
__global__ __launch_bounds__(256)
void sgemm_kernel(const float* __restrict__ A, const float* __restrict__ W,
                  const float* __restrict__ bias, float* __restrict__ out,
                  int Ncols)
{
    __shared__ float As[2][KB][132];   // transposed [k][m], padded
    __shared__ float Bs[2][KB][128];   // natural [k][n]

    const int tid = threadIdx.x;
    const int m0  = blockIdx.y * 128;
    const int c0  = blockIdx.x * 128;
    const int ty  = tid >> 4;          // 0..15 -> rows ty*8..
    const int tx  = tid & 15;          // 0..15 -> cols tx*8..

    const float* Ap = (MODE == 0) ? A : g_AttO;

    // loader lanes
    const int ar = tid >> 1;           // 0..127
    const int ac = (tid & 1) * 8;      // 0 or 8 (two float4 each)
    const int br = tid >> 5;           // 0..7  (+8)
    const int bc = (tid & 31) * 4;     // 0..124

    float acc[8][8];
#pragma unroll
    for (int i = 0; i < 8; i++)
#pragma unroll
        for (int j = 0; j < 8; j++) acc[i][j] = 0.f;

    // ---- prologue: chunk 0 straight to smem buf 0 ----
    {
        float4 a0 = *reinterpret_cast<const float4*>(Ap + (size_t)(m0 + ar) * HDIM + ac);
        float4 a1 = *reinterpret_cast<const float4*>(Ap + (size_t)(m0 + ar) * HDIM + ac + 4);
        float4 b0 = *reinterpret_cast<const float4*>(W + (size_t)br * Ncols + c0 + bc);
        float4 b1 = *reinterpret_cast<const float4*>(W + (size_t)(br + 8) * Ncols + c0 + bc);
        As[0][ac + 0][ar] = a0.x; As[0][ac + 1][ar] = a0.y;
        As[0][ac + 2][ar] = a0.z; As[0][ac + 3][ar] = a0.w;
        As[0][ac + 4][ar] = a1.x; As[0][ac + 5][ar] = a1.y;
        As[0][ac + 6][ar] = a1.z; As[0][ac + 7][ar] = a1.w;
        *reinterpret_cast<float4*>(&Bs[0][br][bc])     = b0;
        *reinterpret_cast<float4*>(&Bs[0][br + 8][bc]) = b1;
    }
    __syncthreads();

    for (int ch = 0; ch < NCHUNK; ch++) {
        const int buf = ch & 1;
        float4 a0, a1, b0, b1;
        if (ch + 1 < NCHUNK) {
            const int kb = (ch + 1) * KB;
            a0 = *reinterpret_cast<const float4*>(Ap + (size_t)(m0 + ar) * HDIM + kb + ac);
            a1 = *reinterpret_cast<const float4*>(Ap + (size_t)(m0 + ar) * HDIM + kb + ac + 4);
            b0 = *reinterpret_cast<const float4*>(W + (size_t)(kb + br) * Ncols + c0 + bc);
            b1 = *reinterpret_cast<const float4*>(W + (size_t)(kb + br + 8) * Ncols + c0 + bc);
        }

#pragma unroll
        for (int k = 0; k < KB; k++) {
            float a[8], b[8];
            *(float4*)&a[0] = *(const float4*)&As[buf][k][ty * 8];
            *(float4*)&a[4] = *(const float4*)&As[buf][k][ty * 8 + 4];
            *(float4*)&b[0] = *(const float4*)&Bs[buf][k][tx * 8];
            *(float4*)&b[4] = *(const float4*)&Bs[buf][k][tx * 8 + 4];
#pragma unroll
            for (int i = 0; i < 8; i++)
#pragma unroll
                for (int j = 0; j < 8; j++) acc[i][j] = fmaf(a[i], b[j], acc[i][j]);
        }

        if (ch + 1 < NCHUNK) {
            const int nb = buf ^ 1;
            As[nb][ac + 0][ar] = a0.x; As[nb][ac + 1][ar] = a0.y;
            As[nb][ac + 2][ar] = a0.z; As[nb][ac + 3][ar] = a0.w;
            As[nb][ac + 4][ar] = a1.x; As[nb][ac + 5][ar] = a1.y;
            As[nb][ac + 6][ar] = a1.z; As[nb][ac + 7][ar] = a1.w;
            *reinterpret_cast<float4*>(&Bs[nb][br][bc])     = b0;
            *reinterpret_cast<float4*>(&Bs[nb][br + 8][bc]) = b1;
        }
        __syncthreads();
    }

    if (MODE == 0) {
        const int cbase = c0 + tx * 8;
        const int part  = cbase / HDIM;                 // 0=Q 1=K 2=V
        const int cc    = cbase - part * HDIM;
        const int h     = cc >> 6;
        const int dbase = cc & 63;
        float* dst = (part == 0) ? g_Q : (part == 1 ? g_K : g_V);
#pragma unroll
        for (int i = 0; i < 8; i++) {
            int m = m0 + ty * 8 + i;
            int bi = m >> 10, n = m & (SEQ - 1);
            float* p = dst + ((size_t)(bi * NHEADS + h) * SEQ + n) * HD + dbase;
#pragma unroll
            for (int j = 0; j < 8; j++) p[j] = acc[i][j] + bias[cbase + j];
        }
    } else {
#pragma unroll
        for (int i = 0; i < 8; i++) {
            int m = m0 + ty * 8 + i;
            float* p = out + (size_t)m * HDIM + c0 + tx * 8;
#pragma unroll
            for (int j = 0; j < 8; j++) p[j] = acc[i][j] + bias[c0 + tx * 8 + j];
        }
    }
}

// ---------------------------------------------------------------------------
// Flash attention (fp32, MUFU-free softmax in log2 domain).
// One block = (b, h, 64-row q tile), 64 threads, 8x8 microtiles.
// Q pre-scaled by log2(e)/sqrt(64) so scores are already in log2 units.
// ---------------------------------------------------------------------------
__global__ __launch_bounds__(64)
void attn_kernel()
{
    __shared__ float Qs[64][64];
    __shared__ float Ks[64][64];
    __shared__ float Vs[64][64];

    const int tid = threadIdx.x;
    const int tx  = tid & 7;
    const int ty  = tid >> 3;
    const int b   = blockIdx.z, h = blockIdx.y;
    const int q0  = blockIdx.x * 64;

    const float* Qg = g_Q + (size_t)((b * NHEADS + h) * SEQ + q0) * HD;
    const float* Kg = g_K + (size_t)((b * NHEADS + h) * SEQ) * HD;
    const float* Vg = g_V + (size_t)((b * NHEADS + h) * SEQ) * HD;

    const float QSCALE = 0.125f * 1.4426950408889634f;  // log2e / sqrt(64)

    for (int f = tid; f < 1024; f += 64) {
        int r = f >> 4, c4 = (f & 15) << 2;
        float4 v = *reinterpret_cast<const float4*>(Qg + r * HD + c4);
        Qs[c4 + 0][r] = v.x * QSCALE; Qs[c4 + 1][r] = v.y * QSCALE;
        Qs[c4 + 2][r] = v.z * QSCALE; Qs[c4 + 3][r] = v.w * QSCALE;
    }

    float o[8][8], mrow[8], lrow[8];
#pragma unroll
    for (int i = 0; i < 8; i++) {
        mrow[i] = -1e30f; lrow[i] = 0.f;
#pragma unroll
        for (int j = 0; j < 8; j++) o[i][j] = 0.f;
    }

    for (int kt = 0; kt < SEQ / 64; kt++) {
        __syncthreads();
        const float* Kt = Kg + (size_t)kt * 64 * HD;
        const float* Vt = Vg + (size_t)kt * 64 * HD;
        for (int f = tid; f < 1024; f += 64) {
            int r = f >> 4, c4 = (f & 15) << 2;
            float4 kv = *reinterpret_cast<const float4*>(Kt + r * HD + c4);
            Ks[c4 + 0][r] = kv.x; Ks[c4 + 1][r] = kv.y;
            Ks[c4 + 2][r] = kv.z; Ks[c4 + 3][r] = kv.w;
            float4 vv = *reinterpret_cast<const float4*>(Vt + r * HD + c4);
            *reinterpret_cast<float4*>(&Vs[r][c4]) = vv;
        }
        __syncthreads();

        float s[8][8];
#pragma unroll
        for (int i = 0; i < 8; i++)
#pragma unroll
            for (int j = 0; j < 8; j++) s[i][j] = 0.f;
        for (int d = 0; d < 64; d++) {
            float qa[8], kb[8];
            *(float4*)&qa[0] = *(const float4*)&Qs[d][ty * 8];
            *(float4*)&qa[4] = *(const float4*)&Qs[d][ty * 8 + 4];
            *(float4*)&kb[0] = *(const float4*)&Ks[d][tx * 8];
            *(float4*)&kb[4] = *(const float4*)&Ks[d][tx * 8 + 4];
#pragma unroll
            for (int i = 0; i < 8; i++)
#pragma unroll
                for (int j = 0; j < 8; j++) s[i][j] = fmaf(qa[i], kb[j], s[i][j]);
        }

#pragma unroll
        for (int i = 0; i < 8; i++) {
            float mx = s[i][0];
#pragma unroll
            for (int j = 1; j < 8; j++) mx = fmaxf(mx, s[i][j]);
            mx = fmaxf(mx, __shfl_xor_sync(0xffffffffu, mx, 1));
            mx = fmaxf(mx, __shfl_xor_sync(0xffffffffu, mx, 2));
            mx = fmaxf(mx, __shfl_xor_sync(0xffffffffu, mx, 4));
            float mnew = fmaxf(mrow[i], mx);
            float corr = exp2f_fast(mrow[i] - mnew);
            float rs = 0.f;
#pragma unroll
            for (int j = 0; j < 8; j++) {
                float p = exp2f_fast(s[i][j] - mnew);
                s[i][j] = p; rs += p;
            }
            rs += __shfl_xor_sync(0xffffffffu, rs, 1);
            rs += __shfl_xor_sync(0xffffffffu, rs, 2);
            rs += __shfl_xor_sync(0xffffffffu, rs, 4);
            lrow[i] = lrow[i] * corr + rs;
            mrow[i] = mnew;
#pragma unroll
            for (int j = 0; j < 8; j++) o[i][j] *= corr;
        }

        __syncthreads();
#pragma unroll
        for (int i = 0; i < 8; i++)
#pragma unroll
            for (int j = 0; j < 8; j++) Ks[tx * 8 + j][ty * 8 + i] = s[i][j];
        __syncthreads();

        for (int k = 0; k < 64; k++) {
            float pa[8], vb[8];
            *(float4*)&pa[0] = *(const float4*)&Ks[k][ty * 8];
            *(float4*)&pa[4] = *(const float4*)&Ks[k][ty * 8 + 4];
            *(float4*)&vb[0] = *(const float4*)&Vs[k][tx * 8];
            *(float4*)&vb[4] = *(const float4*)&Vs[k][tx * 8 + 4];
#pragma unroll
            for (int i = 0; i < 8; i++)
#pragma unroll
                for (int j = 0; j < 8; j++) o[i][j] = fmaf(pa[i], vb[j], o[i][j]);
        }
    }

#pragma unroll
    for (int i = 0; i < 8; i++) {
        float inv = 1.f / lrow[i];
        int n = q0 + ty * 8 + i;
        float* p = g_AttO + (size_t)(b * SEQ + n) * HDIM + h * HD + tx * 8;
#pragma unroll
        for (int j = 0; j < 8; j++) p[j] = o[i][j] * inv;
    }
}

// ---------------------------------------------------------------------------
extern "C" void kernel_launch(void* const* d_in, const int* in_sizes, int n_in,
                              void* d_out, int out_size)
{
    const float* x     = (const float*)d_in[0];
    const float* w_qkv = (const float*)d_in[1];
    const float* b_qkv = (const float*)d_in[2];
    const float* w_out = (const float*)d_in[3];
    const float* b_out = (const float*)d_in[4];
    float* out = (float*)d_out;
    (void)in_sizes; (void)n_in; (void)out_size;

    dim3 g1(QKVN / 128, MTOK / 128);                 // 18 x 128 blocks
    sgemm_kernel<0><<<g1, 256>>>(x, w_qkv, b_qkv, nullptr, QKVN);

    dim3 g2(SEQ / 64, NHEADS, BATCH);                // 16 x 12 x 16 blocks
    attn_kernel<<<g2, 64>>>();

    dim3 g3(HDIM / 128, MTOK / 128);                 // 6 x 128 blocks
    sgemm_kernel<1><<<g3, 256>>>(g_AttO, w_out, b_out, out, HDIM);
}

// round 10
// speedup vs baseline: 1.2398x; 1.2363x over previous
#include <cuda_runtime.h>

#define BATCH  16
#define SEQ    1024
#define HDIM   768
#define NHEADS 12
#define HD     64
#define MTOK   (BATCH*SEQ)      /* 16384 */
#define QKVN   (3*HDIM)         /* 2304  */

// ------------------------- device scratch (no alloc rule) -------------------
__device__ __align__(256) float g_Q[BATCH*NHEADS*SEQ*HD];
__device__ __align__(256) float g_K[BATCH*NHEADS*SEQ*HD];
__device__ __align__(256) float g_V[BATCH*NHEADS*SEQ*HD];
__device__ __align__(256) float g_AttO[MTOK*HDIM];

// Fast exp2 on (-inf, 0]: degree-6 poly + exponent bits. No MUFU.
__device__ __forceinline__ float exp2f_fast(float x) {
    x = fmaxf(x, -125.0f);
    float t = floorf(x);
    float f = x - t;
    float p = 1.5403530e-4f;
    p = fmaf(p, f, 1.3333558e-3f);
    p = fmaf(p, f, 9.6181291e-3f);
    p = fmaf(p, f, 5.5504109e-2f);
    p = fmaf(p, f, 2.4022651e-1f);
    p = fmaf(p, f, 6.9314718e-1f);
    p = fmaf(p, f, 1.0f);
    int e = (int)t;
    return p * __int_as_float((e + 127) << 23);
}

// ---------------------------------------------------------------------------
// SGEMM (round-9 verified): C[M,Ncols] = A[M,768] @ W[768,Ncols] + bias
// 128x128 tile, 256 thr, 8x8 microtile, KB=16 double-buffered w/ reg prefetch.
// ---------------------------------------------------------------------------
#define KB     16
#define NCHUNK (HDIM / KB)      /* 48 */

template<int MODE>
__global__ __launch_bounds__(256)
void sgemm_kernel(const float* __restrict__ A, const float* __restrict__ W,
                  const float* __restrict__ bias, float* __restrict__ out,
                  int Ncols)
{
    __shared__ float As[2][KB][132];
    __shared__ float Bs[2][KB][128];

    const int tid = threadIdx.x;
    const int m0  = blockIdx.y * 128;
    const int c0  = blockIdx.x * 128;
    const int ty  = tid >> 4;
    const int tx  = tid & 15;

    const float* Ap = (MODE == 0) ? A : g_AttO;

    const int ar = tid >> 1;
    const int ac = (tid & 1) * 8;
    const int br = tid >> 5;
    const int bc = (tid & 31) * 4;

    float acc[8][8];
#pragma unroll
    for (int i = 0; i < 8; i++)
#pragma unroll
        for (int j = 0; j < 8; j++) acc[i][j] = 0.f;

    {
        float4 a0 = *reinterpret_cast<const float4*>(Ap + (size_t)(m0 + ar) * HDIM + ac);
        float4 a1 = *reinterpret_cast<const float4*>(Ap + (size_t)(m0 + ar) * HDIM + ac + 4);
        float4 b0 = *reinterpret_cast<const float4*>(W + (size_t)br * Ncols + c0 + bc);
        float4 b1 = *reinterpret_cast<const float4*>(W + (size_t)(br + 8) * Ncols + c0 + bc);
        As[0][ac + 0][ar] = a0.x; As[0][ac + 1][ar] = a0.y;
        As[0][ac + 2][ar] = a0.z; As[0][ac + 3][ar] = a0.w;
        As[0][ac + 4][ar] = a1.x; As[0][ac + 5][ar] = a1.y;
        As[0][ac + 6][ar] = a1.z; As[0][ac + 7][ar] = a1.w;
        *reinterpret_cast<float4*>(&Bs[0][br][bc])     = b0;
        *reinterpret_cast<float4*>(&Bs[0][br + 8][bc]) = b1;
    }
    __syncthreads();

    for (int ch = 0; ch < NCHUNK; ch++) {
        const int buf = ch & 1;
        float4 a0, a1, b0, b1;
        if (ch + 1 < NCHUNK) {
            const int kb = (ch + 1) * KB;
            a0 = *reinterpret_cast<const float4*>(Ap + (size_t)(m0 + ar) * HDIM + kb + ac);
            a1 = *reinterpret_cast<const float4*>(Ap + (size_t)(m0 + ar) * HDIM + kb + ac + 4);
            b0 = *reinterpret_cast<const float4*>(W + (size_t)(kb + br) * Ncols + c0 + bc);
            b1 = *reinterpret_cast<const float4*>(W + (size_t)(kb + br + 8) * Ncols + c0 + bc);
        }

#pragma unroll
        for (int k = 0; k < KB; k++) {
            float a[8], b[8];
            *(float4*)&a[0] = *(const float4*)&As[buf][k][ty * 8];
            *(float4*)&a[4] = *(const float4*)&As[buf][k][ty * 8 + 4];
            *(float4*)&b[0] = *(const float4*)&Bs[buf][k][tx * 8];
            *(float4*)&b[4] = *(const float4*)&Bs[buf][k][tx * 8 + 4];
#pragma unroll
            for (int i = 0; i < 8; i++)
#pragma unroll
                for (int j = 0; j < 8; j++) acc[i][j] = fmaf(a[i], b[j], acc[i][j]);
        }

        if (ch + 1 < NCHUNK) {
            const int nb = buf ^ 1;
            As[nb][ac + 0][ar] = a0.x; As[nb][ac + 1][ar] = a0.y;
            As[nb][ac + 2][ar] = a0.z; As[nb][ac + 3][ar] = a0.w;
            As[nb][ac + 4][ar] = a1.x; As[nb][ac + 5][ar] = a1.y;
            As[nb][ac + 6][ar] = a1.z; As[nb][ac + 7][ar] = a1.w;
            *reinterpret_cast<float4*>(&Bs[nb][br][bc])     = b0;
            *reinterpret_cast<float4*>(&Bs[nb][br + 8][bc]) = b1;
        }
        __syncthreads();
    }

    if (MODE == 0) {
        const int cbase = c0 + tx * 8;
        const int part  = cbase / HDIM;
        const int cc    = cbase - part * HDIM;
        const int h     = cc >> 6;
        const int dbase = cc & 63;
        float* dst = (part == 0) ? g_Q : (part == 1 ? g_K : g_V);
#pragma unroll
        for (int i = 0; i < 8; i++) {
            int m = m0 + ty * 8 + i;
            int bi = m >> 10, n = m & (SEQ - 1);
            float* p = dst + ((size_t)(bi * NHEADS + h) * SEQ + n) * HD + dbase;
#pragma unroll
            for (int j = 0; j < 8; j++) p[j] = acc[i][j] + bias[cbase + j];
        }
    } else {
#pragma unroll
        for (int i = 0; i < 8; i++) {
            int m = m0 + ty * 8 + i;
            float* p = out + (size_t)m * HDIM + c0 + tx * 8;
#pragma unroll
            for (int j = 0; j < 8; j++) p[j] = acc[i][j] + bias[c0 + tx * 8 + j];
        }
    }
}

// ---------------------------------------------------------------------------
// Flash attention, 128 threads/block (4 warps), 64x64 tile, 8x4 microtile.
// ty = tid>>4 (8 row groups of 8), tx = tid&15 (16 col groups of 4).
// Qs [d][q] (pre-scaled by log2e/8). Ks: K phase = [d][kv] XOR-swizzled
// (group' = ((kv>>2)+(d>>2))&15) so transposed staging stores are ~2-way;
// P phase reuses Ks as natural [q][kv]. Vs natural [kv][d].
// Smem = 3*64*64*4 = 48KB. ~110 regs -> 4 blocks/SM = 512 thr/SM.
// ---------------------------------------------------------------------------
__global__ __launch_bounds__(128)
void attn_kernel()
{
    __shared__ float Qs[64][64];
    __shared__ float Ks[64][64];
    __shared__ float Vs[64][64];

    const int tid = threadIdx.x;
    const int tx  = tid & 15;      // col group: cols tx*4..+3
    const int ty  = tid >> 4;      // row group: rows ty*8..+7
    const int b   = blockIdx.z, h = blockIdx.y;
    const int q0  = blockIdx.x * 64;

    const float* Qg = g_Q + (size_t)((b * NHEADS + h) * SEQ + q0) * HD;
    const float* Kg = g_K + (size_t)((b * NHEADS + h) * SEQ) * HD;
    const float* Vg = g_V + (size_t)((b * NHEADS + h) * SEQ) * HD;

    const float QSCALE = 0.125f * 1.4426950408889634f;  // log2e / sqrt(64)
    float* ksf = &Ks[0][0];

    // Q staging: transposed [d][q], pre-scaled (one-time)
    for (int f = tid; f < 1024; f += 128) {
        int r = f >> 4, c4 = (f & 15) << 2;
        float4 v = *reinterpret_cast<const float4*>(Qg + r * HD + c4);
        Qs[c4 + 0][r] = v.x * QSCALE; Qs[c4 + 1][r] = v.y * QSCALE;
        Qs[c4 + 2][r] = v.z * QSCALE; Qs[c4 + 3][r] = v.w * QSCALE;
    }

    float o[8][4], mrow[8], lrow[8];
#pragma unroll
    for (int i = 0; i < 8; i++) {
        mrow[i] = -1e30f; lrow[i] = 0.f;
#pragma unroll
        for (int j = 0; j < 4; j++) o[i][j] = 0.f;
    }

    for (int kt = 0; kt < SEQ / 64; kt++) {
        __syncthreads();                       // prev iter done with Ks/Vs
        const float* Kt = Kg + (size_t)kt * 64 * HD;
        const float* Vt = Vg + (size_t)kt * 64 * HD;
        for (int f = tid; f < 1024; f += 128) {
            int r  = f >> 4;                   // kv row 0..63
            int c4 = (f & 15) << 2;            // d chunk base
            float4 kv = *reinterpret_cast<const float4*>(Kt + r * HD + c4);
            // swizzled transposed store: element (d=c4+i, kv=r)
            int sg   = ((r >> 2) + (c4 >> 2)) & 15;
            int base = sg * 4 + (r & 3);
            ksf[(c4 + 0) * 64 + base] = kv.x;
            ksf[(c4 + 1) * 64 + base] = kv.y;
            ksf[(c4 + 2) * 64 + base] = kv.z;
            ksf[(c4 + 3) * 64 + base] = kv.w;
            float4 vv = *reinterpret_cast<const float4*>(Vt + r * HD + c4);
            *reinterpret_cast<float4*>(&Vs[r][c4]) = vv;
        }
        __syncthreads();

        // S = Qscaled @ K^T  (8x4 per thread)
        float s[8][4];
#pragma unroll
        for (int i = 0; i < 8; i++)
#pragma unroll
            for (int j = 0; j < 4; j++) s[i][j] = 0.f;
#pragma unroll 4
        for (int d = 0; d < 64; d++) {
            float qa[8], kb[4];
            *(float4*)&qa[0] = *(const float4*)&Qs[d][ty * 8];
            *(float4*)&qa[4] = *(const float4*)&Qs[d][ty * 8 + 4];
            int g = (tx + (d >> 2)) & 15;
            *(float4*)&kb[0] = *(const float4*)&ksf[d * 64 + g * 4];
#pragma unroll
            for (int i = 0; i < 8; i++)
#pragma unroll
                for (int j = 0; j < 4; j++) s[i][j] = fmaf(qa[i], kb[j], s[i][j]);
        }

        // online softmax (row stats across the 16 lanes sharing ty)
#pragma unroll
        for (int i = 0; i < 8; i++) {
            float mx = fmaxf(fmaxf(s[i][0], s[i][1]), fmaxf(s[i][2], s[i][3]));
            mx = fmaxf(mx, __shfl_xor_sync(0xffffffffu, mx, 1));
            mx = fmaxf(mx, __shfl_xor_sync(0xffffffffu, mx, 2));
            mx = fmaxf(mx, __shfl_xor_sync(0xffffffffu, mx, 4));
            mx = fmaxf(mx, __shfl_xor_sync(0xffffffffu, mx, 8));
            float mnew = fmaxf(mrow[i], mx);
            float corr = exp2f_fast(mrow[i] - mnew);
            float rs = 0.f;
#pragma unroll
            for (int j = 0; j < 4; j++) {
                float p = exp2f_fast(s[i][j] - mnew);
                s[i][j] = p; rs += p;
            }
            rs += __shfl_xor_sync(0xffffffffu, rs, 1);
            rs += __shfl_xor_sync(0xffffffffu, rs, 2);
            rs += __shfl_xor_sync(0xffffffffu, rs, 4);
            rs += __shfl_xor_sync(0xffffffffu, rs, 8);
            lrow[i] = lrow[i] * corr + rs;
            mrow[i] = mnew;
#pragma unroll
            for (int j = 0; j < 4; j++) o[i][j] *= corr;
        }

        __syncthreads();                       // done reading Ks as K
        // P staged natural [q][kv] into Ks buffer (float4 row stores)
#pragma unroll
        for (int i = 0; i < 8; i++) {
            float4 pv;
            pv.x = s[i][0]; pv.y = s[i][1]; pv.z = s[i][2]; pv.w = s[i][3];
            *reinterpret_cast<float4*>(&Ks[ty * 8 + i][tx * 4]) = pv;
        }
        __syncthreads();

        // O += P @ V
#pragma unroll 4
        for (int k = 0; k < 64; k++) {
            float pa[8], vb[4];
#pragma unroll
            for (int i = 0; i < 8; i++) pa[i] = Ks[ty * 8 + i][k];
            *(float4*)&vb[0] = *(const float4*)&Vs[k][tx * 4];
#pragma unroll
            for (int i = 0; i < 8; i++)
#pragma unroll
                for (int j = 0; j < 4; j++) o[i][j] = fmaf(pa[i], vb[j], o[i][j]);
        }
    }

    // normalize + write [B, N, H] (heads concatenated), float4 per row
#pragma unroll
    for (int i = 0; i < 8; i++) {
        float inv = 1.f / lrow[i];
        int n = q0 + ty * 8 + i;
        float4 v;
        v.x = o[i][0] * inv; v.y = o[i][1] * inv;
        v.z = o[i][2] * inv; v.w = o[i][3] * inv;
        *reinterpret_cast<float4*>(
            g_AttO + (size_t)(b * SEQ + n) * HDIM + h * HD + tx * 4) = v;
    }
}

// ---------------------------------------------------------------------------
extern "C" void kernel_launch(void* const* d_in, const int* in_sizes, int n_in,
                              void* d_out, int out_size)
{
    const float* x     = (const float*)d_in[0];
    const float* w_qkv = (const float*)d_in[1];
    const float* b_qkv = (const float*)d_in[2];
    const float* w_out = (const float*)d_in[3];
    const float* b_out = (const float*)d_in[4];
    float* out = (float*)d_out;
    (void)in_sizes; (void)n_in; (void)out_size;

    dim3 g1(QKVN / 128, MTOK / 128);
    sgemm_kernel<0><<<g1, 256>>>(x, w_qkv, b_qkv, nullptr, QKVN);

    dim3 g2(SEQ / 64, NHEADS, BATCH);
    attn_kernel<<<g2, 128>>>();

    dim3 g3(HDIM / 128, MTOK / 128);
    sgemm_kernel<1><<<g3, 256>>>(g_AttO, w_out, b_out, out, HDIM);
}